// round 14
// baseline (speedup 1.0000x reference)
#include <cuda_runtime.h>
#include <cuda_bf16.h>

#define N_NODESC 50000
#define N_EDGESC 400000
#define SCAN_BLKS 49   // ceil(50000/1024)
#define AGG_BLKS 592   // persistent agg grid (4/SM)

typedef unsigned int u32;
typedef unsigned long long u64;

// ---------------- device scratch ----------------
__device__ u64   g_xs[(size_t)N_NODESC * 64];     // x split: [row][pair] (hi|lo packed u64)
__device__ float g_Aarr[(size_t)N_NODESC * 256];  // A-half of edge pre-act (+b_edge)
__device__ float g_Barr[(size_t)N_NODESC * 256];  // B-half (gathered randomly; L2-resident)
__device__ u64   g_nas[(size_t)N_NODESC * 64];    // node_agg split
__device__ u64   g_eas[(size_t)N_NODESC * 128];   // edge_agg split
__device__ u64   g_hs[(size_t)N_NODESC * 192];    // h split
__device__ float g_h2[(size_t)N_NODESC * 32];
__device__ u64   g_Wcs[64 * 512];                 // Wc split  [pair][n]
__device__ u64   g_Wns[64 * 256];
__device__ u64   g_Wes[128 * 128];
__device__ u64   g_Wfs[192 * 32];
__device__ float g_bc[512];
__device__ int   g_count[N_NODESC];
__device__ int   g_off[N_NODESC + 1];
__device__ int   g_cur[N_NODESC];
__device__ int   g_csr[N_EDGESC];
__device__ int   g_ei32[2 * N_EDGESC];
__device__ int   g_bsum[SCAN_BLKS];
__device__ int   g_bpre[SCAN_BLKS];
__device__ int   g_dtype_flag;

// ---------------- helpers ----------------
__device__ __forceinline__ u64 splitpair(float a, float b) {
    __nv_bfloat162 h = __float22bfloat162_rn(make_float2(a, b));
    float2 hf = __bfloat1622float2(h);
    __nv_bfloat162 l = __float22bfloat162_rn(make_float2(a - hf.x, b - hf.y));
    u32 hw = *(u32*)&h, lw = *(u32*)&l;
    return (u64)hw | ((u64)lw << 32);
}

__device__ __forceinline__ void mma16816(float* d, const u32* a, const u32* b) {
    asm volatile(
        "mma.sync.aligned.m16n8k16.row.col.f32.bf16.bf16.f32 "
        "{%0,%1,%2,%3}, {%4,%5,%6,%7}, {%8,%9}, {%0,%1,%2,%3};\n"
        : "+f"(d[0]), "+f"(d[1]), "+f"(d[2]), "+f"(d[3])
        : "r"(a[0]), "r"(a[1]), "r"(a[2]), "r"(a[3]), "r"(b[0]), "r"(b[1]));
}

// 16-byte cp.async (cg = L2 path). pred=false -> zero-fill.
__device__ __forceinline__ void cpasync16(u32 saddr, const void* g, bool pred) {
    int sz = pred ? 16 : 0;
    asm volatile("cp.async.cg.shared.global [%0], [%1], 16, %2;\n"
                 :: "r"(saddr), "l"(g), "r"(sz));
}
#define CP_COMMIT() asm volatile("cp.async.commit_group;\n")
#define CP_WAIT1()  asm volatile("cp.async.wait_group 1;\n")

// ---------------- zero init (tiny; gate for the CSR branch) ----------------
__global__ void zero_kernel() {
    int i = blockIdx.x * blockDim.x + threadIdx.x;
    if (i < N_NODESC) g_count[i] = 0;
    if (i == 0) g_dtype_flag = 0;
}

// ---------------- split weights + split x ----------------
__device__ __forceinline__ float wcval(const float* We, int k, int n) {
    return (n < 256) ? (We[k * 256 + n] - We[(128 + k) * 256 + n])
                     : We[(128 + k) * 256 + (n - 256)];
}

#define SPLITX_BLKS 12500   // N_NODESC*64/256
#define PREPW_BLKS  128

__global__ void setup_kernel(const float* __restrict__ x,
                             const float* __restrict__ We, const float* __restrict__ be,
                             const float* __restrict__ Wn, const float* __restrict__ Wd,
                             const float* __restrict__ Wf) {
    int b = blockIdx.x, tid = threadIdx.x;
    if (b < SPLITX_BLKS) {
        int idx = b * 256 + tid;
        int row = idx >> 6, c = idx & 63;
        float2 v = *(const float2*)(x + (size_t)row * 128 + 2 * c);
        g_xs[idx] = splitpair(v.x, v.y);
    } else {
        int idx = (b - SPLITX_BLKS) * 256 + tid;   // 0..32767
        {
            int c = idx >> 9, n = idx & 511;
            g_Wcs[idx] = splitpair(wcval(We, 2 * c, n), wcval(We, 2 * c + 1, n));
        }
        if (idx < 64 * 256) {
            int c = idx >> 8, n = idx & 255;
            g_Wns[idx] = splitpair(Wn[2 * c * 256 + n], Wn[(2 * c + 1) * 256 + n]);
        }
        if (idx < 128 * 128) {
            int c = idx >> 7, n = idx & 127;
            g_Wes[idx] = splitpair(Wd[2 * c * 128 + n], Wd[(2 * c + 1) * 128 + n]);
        }
        if (idx < 192 * 32) {
            int c = idx >> 5, n = idx & 31;
            g_Wfs[idx] = splitpair(Wf[2 * c * 32 + n], Wf[(2 * c + 1) * 32 + n]);
        }
        if (idx < 512) g_bc[idx] = (idx < 256) ? be[idx] : 0.0f;
    }
}

// ---------------- dtype detect / convert+hist ----------------
__global__ void detect_kernel(const int* __restrict__ w) {
    int acc = 0;
    for (int i = blockIdx.x * blockDim.x + threadIdx.x; i < N_EDGESC; i += gridDim.x * blockDim.x)
        acc |= w[2 * i + 1];
    #pragma unroll
    for (int o = 16; o; o >>= 1) acc |= __shfl_xor_sync(0xffffffffu, acc, o);
    if ((threadIdx.x & 31) == 0 && acc) atomicOr(&g_dtype_flag, 1);
}

__global__ void conv_hist_kernel(const void* __restrict__ ei) {
    int e = blockIdx.x * blockDim.x + threadIdx.x;
    if (e < N_EDGESC) {
        int s, d;
        if (g_dtype_flag) {
            s = ((const int*)ei)[e];
            d = ((const int*)ei)[N_EDGESC + e];
        } else {
            s = (int)((const long long*)ei)[e];
            d = (int)((const long long*)ei)[N_EDGESC + e];
        }
        g_ei32[e] = s;
        g_ei32[N_EDGESC + e] = d;
        atomicAdd(&g_count[d], 1);
    }
}

// ---------------- parallel scan ----------------
__global__ void scan1_kernel() {
    __shared__ int wsum[32], wpre[32];
    int tid = threadIdx.x, lane = tid & 31, w = tid >> 5;
    int i = blockIdx.x * 1024 + tid;
    int orig = (i < N_NODESC) ? g_count[i] : 0;
    int v = orig;
    #pragma unroll
    for (int o = 1; o < 32; o <<= 1) {
        int t = __shfl_up_sync(0xffffffffu, v, o);
        if (lane >= o) v += t;
    }
    if (lane == 31) wsum[w] = v;
    __syncthreads();
    if (w == 0) {
        int s = wsum[lane], sv = s;
        #pragma unroll
        for (int o = 1; o < 32; o <<= 1) {
            int t = __shfl_up_sync(0xffffffffu, sv, o);
            if (lane >= o) sv += t;
        }
        wpre[lane] = sv - s;
        if (lane == 31) g_bsum[blockIdx.x] = sv;
    }
    __syncthreads();
    if (i < N_NODESC) {
        int ex = wpre[w] + v - orig;
        g_off[i] = ex;
        g_cur[i] = ex;
    }
}

__global__ void scan2_kernel() {
    __shared__ int s[64];
    int tid = threadIdx.x;
    int orig = (tid < SCAN_BLKS) ? g_bsum[tid] : 0;
    s[tid] = orig;
    __syncthreads();
    #pragma unroll
    for (int o = 1; o < 64; o <<= 1) {
        int t = (tid >= o) ? s[tid - o] : 0;
        __syncthreads();
        s[tid] += t;
        __syncthreads();
    }
    if (tid < SCAN_BLKS) g_bpre[tid] = s[tid] - orig;
    if (tid == 63) g_off[N_NODESC] = s[63];
}

__global__ void scan3_kernel() {
    int i = blockIdx.x * blockDim.x + threadIdx.x;
    if (i < N_NODESC) {
        int add = g_bpre[i >> 10];
        g_off[i] += add;
        g_cur[i] += add;
    }
}

__global__ void scatter_kernel() {
    int e = blockIdx.x * blockDim.x + threadIdx.x;
    if (e < N_EDGESC) {
        int d = g_ei32[N_EDGESC + e];
        int s = g_ei32[e];
        int p = atomicAdd(&g_cur[d], 1);
        g_csr[p] = s;
    }
}

// ---------------- 2-stage cp.async tensor-core GEMM (proven config) ----------------
// OMODE: 0 = fp32 out, 1 = split-u64 out, 2 = AB dual fp32 (Aarr/Barr)
template <int BM, int BN, int WM, int WN, bool RELU, int OMODE>
__global__ __launch_bounds__(256, 3) void mma_gemm(
    const u64* __restrict__ As,      // [M][K/2]
    const u64* __restrict__ Ws,      // [K/2][Nfull]
    const float* __restrict__ bias,
    float* __restrict__ outf, u64* __restrict__ outs, float* __restrict__ outf2,
    int ldo_p, int ocol0, int M, int K, int Nfull)
{
    constexpr int PC = 8;
    constexpr int SRA = 12;
    constexpr int SRW = BN + 4;
    constexpr int WARPS_N = BN / WN;
    constexpr int MT = WM / 16, NT = WN / 8;
    static_assert((BM / WM) * (BN / WN) == 8, "warp grid must cover block tile");
    constexpr int A_OPS = BM * PC / 2;
    constexpr int W_OPS = PC * BN / 2;
    __shared__ u64 Asm[2][BM][SRA];
    __shared__ u64 Wsm[2][PC][SRW];

    int tid = threadIdx.x;
    int w = tid >> 5, lane = tid & 31;
    int gr = lane >> 2, thc = lane & 3;
    int wm = w / WARPS_N, wn = w % WARPS_N;
    int m0 = blockIdx.y * BM, n0 = blockIdx.x * BN;
    int m0w = wm * WM, n0w = wn * WN;
    int Kp = K >> 1, NS = Kp / PC;

    float d[MT][NT][4] = {};

    auto issue_stage = [&](int buf, int p0) {
        #pragma unroll
        for (int j = 0; j < (A_OPS + 255) / 256; j++) {
            int p = tid + j * 256;
            if ((A_OPS % 256 == 0) || p < A_OPS) {
                int row = p >> 2, dc = (p & 3) * 2;
                u32 sa = (u32)__cvta_generic_to_shared(&Asm[buf][row][dc]);
                cpasync16(sa, As + (size_t)(m0 + row) * Kp + p0 + dc, (m0 + row) < M);
            }
        }
        #pragma unroll
        for (int j = 0; j < (W_OPS + 255) / 256; j++) {
            int p = tid + j * 256;
            if ((W_OPS % 256 == 0) || p < W_OPS) {
                int c = p / (BN / 2), dn = (p % (BN / 2)) * 2;
                u32 sa = (u32)__cvta_generic_to_shared(&Wsm[buf][c][dn]);
                cpasync16(sa, Ws + (size_t)(p0 + c) * Nfull + n0 + dn, true);
            }
        }
        CP_COMMIT();
    };

    issue_stage(0, 0);
    for (int s = 0; s < NS; s++) {
        int buf = s & 1;
        if (s + 1 < NS) issue_stage(buf ^ 1, (s + 1) * PC);
        else CP_COMMIT();
        CP_WAIT1();
        __syncthreads();

        u32 ah[MT][4], al[MT][4], bh[NT][2], bl[NT][2];
        #pragma unroll
        for (int i = 0; i < MT; i++) {
            int r0 = m0w + 16 * i + gr, r1 = r0 + 8;
            u64 v0 = Asm[buf][r0][thc],     v1 = Asm[buf][r1][thc];
            u64 v2 = Asm[buf][r0][thc + 4], v3 = Asm[buf][r1][thc + 4];
            ah[i][0] = (u32)v0; al[i][0] = (u32)(v0 >> 32);
            ah[i][1] = (u32)v1; al[i][1] = (u32)(v1 >> 32);
            ah[i][2] = (u32)v2; al[i][2] = (u32)(v2 >> 32);
            ah[i][3] = (u32)v3; al[i][3] = (u32)(v3 >> 32);
        }
        #pragma unroll
        for (int j = 0; j < NT; j++) {
            int nn = n0w + 8 * j + gr;
            u64 v0 = Wsm[buf][thc][nn], v1 = Wsm[buf][thc + 4][nn];
            bh[j][0] = (u32)v0; bl[j][0] = (u32)(v0 >> 32);
            bh[j][1] = (u32)v1; bl[j][1] = (u32)(v1 >> 32);
        }
        #pragma unroll
        for (int i = 0; i < MT; i++)
            #pragma unroll
            for (int j = 0; j < NT; j++) {
                mma16816(d[i][j], ah[i], bh[j]);
                mma16816(d[i][j], ah[i], bl[j]);
                mma16816(d[i][j], al[i], bh[j]);
            }
        __syncthreads();
    }

    #pragma unroll
    for (int i = 0; i < MT; i++) {
        int row0 = m0 + m0w + 16 * i + gr;
        int row1 = row0 + 8;
        #pragma unroll
        for (int j = 0; j < NT; j++) {
            int col = n0 + n0w + 8 * j + 2 * thc;
            float b0 = bias[col], b1 = bias[col + 1];
            float v00 = d[i][j][0] + b0, v01 = d[i][j][1] + b1;
            float v10 = d[i][j][2] + b0, v11 = d[i][j][3] + b1;
            if (RELU) {
                v00 = fmaxf(v00, 0.0f); v01 = fmaxf(v01, 0.0f);
                v10 = fmaxf(v10, 0.0f); v11 = fmaxf(v11, 0.0f);
            }
            if (OMODE == 0) {
                if (row0 < M) *(float2*)(outf + (size_t)row0 * ldo_p + col) = make_float2(v00, v01);
                if (row1 < M) *(float2*)(outf + (size_t)row1 * ldo_p + col) = make_float2(v10, v11);
            } else if (OMODE == 1) {
                int pidx = (ocol0 + col) >> 1;
                if (row0 < M) outs[(size_t)row0 * ldo_p + pidx] = splitpair(v00, v01);
                if (row1 < M) outs[(size_t)row1 * ldo_p + pidx] = splitpair(v10, v11);
            } else {
                float* dst = (col < 256) ? outf : outf2;
                int cc = (col < 256) ? col : col - 256;
                if (row0 < M) *(float2*)(dst + (size_t)row0 * 256 + cc) = make_float2(v00, v01);
                if (row1 < M) *(float2*)(dst + (size_t)row1 * 256 + cc) = make_float2(v10, v11);
            }
        }
    }
}

// ---------------- node aggregation (persistent strided; unroll x2) ----------------
__global__ void node_agg_kernel(const float* __restrict__ x) {
    int gw = (blockIdx.x * blockDim.x + threadIdx.x) >> 5;
    int lane = threadIdx.x & 31;
    const int GW = AGG_BLKS * 8;
    for (int d = gw; d < N_NODESC; d += GW) {
        int beg = g_off[d], end = g_off[d + 1];
        float4 na = make_float4(0, 0, 0, 0);
        int e = beg;
        for (; e + 1 < end; e += 2) {
            int s0 = g_csr[e], s1 = g_csr[e + 1];
            float4 x0 = ((const float4*)(x + (size_t)s0 * 128))[lane];
            float4 x1 = ((const float4*)(x + (size_t)s1 * 128))[lane];
            na.x += x0.x + x1.x; na.y += x0.y + x1.y;
            na.z += x0.z + x1.z; na.w += x0.w + x1.w;
        }
        if (e < end) {
            int s0 = g_csr[e];
            float4 x0 = ((const float4*)(x + (size_t)s0 * 128))[lane];
            na.x += x0.x; na.y += x0.y; na.z += x0.z; na.w += x0.w;
        }
        u64* nw = g_nas + (size_t)d * 64;
        nw[2 * lane]     = splitpair(na.x, na.y);
        nw[2 * lane + 1] = splitpair(na.z, na.w);
    }
}

// ---------------- edge aggregation (persistent strided; unroll x2) ----------------
__global__ void edge_agg_kernel() {
    int gw = (blockIdx.x * blockDim.x + threadIdx.x) >> 5;
    int lane = threadIdx.x & 31;
    const int GW = AGG_BLKS * 8;
    for (int d = gw; d < N_NODESC; d += GW) {
        int beg = g_off[d], end = g_off[d + 1];
        const float4* Ar = (const float4*)(g_Aarr + (size_t)d * 256);
        float4 a0 = Ar[lane], a1 = Ar[32 + lane];
        float4 e0 = make_float4(0, 0, 0, 0), e1 = e0;
        int e = beg;
        for (; e + 1 < end; e += 2) {
            int s0 = g_csr[e], s1 = g_csr[e + 1];
            const float4* br0 = (const float4*)(g_Barr + (size_t)s0 * 256);
            const float4* br1 = (const float4*)(g_Barr + (size_t)s1 * 256);
            float4 p0 = br0[lane], p1 = br0[32 + lane];
            float4 q0 = br1[lane], q1 = br1[32 + lane];
            e0.x += fmaxf(a0.x + p0.x, 0.0f) + fmaxf(a0.x + q0.x, 0.0f);
            e0.y += fmaxf(a0.y + p0.y, 0.0f) + fmaxf(a0.y + q0.y, 0.0f);
            e0.z += fmaxf(a0.z + p0.z, 0.0f) + fmaxf(a0.z + q0.z, 0.0f);
            e0.w += fmaxf(a0.w + p0.w, 0.0f) + fmaxf(a0.w + q0.w, 0.0f);
            e1.x += fmaxf(a1.x + p1.x, 0.0f) + fmaxf(a1.x + q1.x, 0.0f);
            e1.y += fmaxf(a1.y + p1.y, 0.0f) + fmaxf(a1.y + q1.y, 0.0f);
            e1.z += fmaxf(a1.z + p1.z, 0.0f) + fmaxf(a1.z + q1.z, 0.0f);
            e1.w += fmaxf(a1.w + p1.w, 0.0f) + fmaxf(a1.w + q1.w, 0.0f);
        }
        if (e < end) {
            int s0 = g_csr[e];
            const float4* br0 = (const float4*)(g_Barr + (size_t)s0 * 256);
            float4 p0 = br0[lane], p1 = br0[32 + lane];
            e0.x += fmaxf(a0.x + p0.x, 0.0f);
            e0.y += fmaxf(a0.y + p0.y, 0.0f);
            e0.z += fmaxf(a0.z + p0.z, 0.0f);
            e0.w += fmaxf(a0.w + p0.w, 0.0f);
            e1.x += fmaxf(a1.x + p1.x, 0.0f);
            e1.y += fmaxf(a1.y + p1.y, 0.0f);
            e1.z += fmaxf(a1.z + p1.z, 0.0f);
            e1.w += fmaxf(a1.w + p1.w, 0.0f);
        }
        u64* ew = g_eas + (size_t)d * 128;
        ew[2 * lane]          = splitpair(e0.x, e0.y);
        ew[2 * lane + 1]      = splitpair(e0.z, e0.w);
        ew[64 + 2 * lane]     = splitpair(e1.x, e1.y);
        ew[64 + 2 * lane + 1] = splitpair(e1.z, e1.w);
    }
}

// ---------------- final sigmoid ----------------
__global__ void sigmoid_kernel(const float* __restrict__ Wf2, const float* __restrict__ bf2,
                               float* __restrict__ out) {
    int gw = (blockIdx.x * blockDim.x + threadIdx.x) >> 5;
    int lane = threadIdx.x & 31;
    if (gw >= N_NODESC) return;
    float t = g_h2[(size_t)gw * 32 + lane] * Wf2[lane];
    #pragma unroll
    for (int o = 16; o; o >>= 1) t += __shfl_xor_sync(0xffffffffu, t, o);
    if (lane == 0) out[gw] = 1.0f / (1.0f + __expf(-(t + bf2[0])));
}

// ---------------- launch (two-branch fork-join; graph-capture-legal) ----------------
extern "C" void kernel_launch(void* const* d_in, const int* in_sizes, int n_in,
                              void* d_out, int out_size) {
    const float* x  = (const float*)d_in[0];
    const void*  ei = d_in[1];
    const float* W_node = (const float*)d_in[3];
    const float* b_node = (const float*)d_in[4];
    const float* W_edge = (const float*)d_in[5];
    const float* b_edge = (const float*)d_in[6];
    const float* W_ed   = (const float*)d_in[7];
    const float* b_ed   = (const float*)d_in[8];
    const float* W_f1   = (const float*)d_in[9];
    const float* b_f1   = (const float*)d_in[10];
    const float* W_f2   = (const float*)d_in[11];
    const float* b_f2   = (const float*)d_in[12];
    float* out = (float*)d_out;

    u64 *pxs, *pnas, *peas, *phs, *pWcs, *pWns, *pWes, *pWfs;
    float *pA, *pB, *pbc, *ph2;
    cudaGetSymbolAddress((void**)&pxs,  g_xs);
    cudaGetSymbolAddress((void**)&pnas, g_nas);
    cudaGetSymbolAddress((void**)&peas, g_eas);
    cudaGetSymbolAddress((void**)&phs,  g_hs);
    cudaGetSymbolAddress((void**)&pWcs, g_Wcs);
    cudaGetSymbolAddress((void**)&pWns, g_Wns);
    cudaGetSymbolAddress((void**)&pWes, g_Wes);
    cudaGetSymbolAddress((void**)&pWfs, g_Wfs);
    cudaGetSymbolAddress((void**)&pA,   g_Aarr);
    cudaGetSymbolAddress((void**)&pB,   g_Barr);
    cudaGetSymbolAddress((void**)&pbc,  g_bc);
    cudaGetSymbolAddress((void**)&ph2,  g_h2);

    const int MB64 = (N_NODESC + 63) / 64;     // 782

    static cudaStream_t s_aux = 0;
    static cudaEvent_t ev_zero = 0, ev_setup = 0, ev_csr = 0, ev_node = 0;
    if (!s_aux) {
        cudaStreamCreateWithFlags(&s_aux, cudaStreamNonBlocking);
        cudaEventCreateWithFlags(&ev_zero,  cudaEventDisableTiming);
        cudaEventCreateWithFlags(&ev_setup, cudaEventDisableTiming);
        cudaEventCreateWithFlags(&ev_csr,   cudaEventDisableTiming);
        cudaEventCreateWithFlags(&ev_node,  cudaEventDisableTiming);
    }

    // main: zero -> fork
    zero_kernel<<<(N_NODESC + 255) / 256, 256>>>();
    cudaEventRecord(ev_zero, 0);
    cudaStreamWaitEvent(s_aux, ev_zero, 0);

    // main: setup (splits + weights) -> AB GEMM
    setup_kernel<<<SPLITX_BLKS + PREPW_BLKS, 256>>>(x, W_edge, b_edge, W_node, W_ed, W_f1);
    cudaEventRecord(ev_setup, 0);
    mma_gemm<64, 128, 32, 32, false, 2><<<dim3(4, MB64), 256>>>(
        pxs, pWcs, pbc, pA, (u64*)0, pB, 0, 0, N_NODESC, 128, 512);

    // aux: CSR chain -> node_agg -> node GEMM (hidden under main's AB+edge_agg)
    detect_kernel<<<256, 256, 0, s_aux>>>((const int*)ei);
    conv_hist_kernel<<<(N_EDGESC + 255) / 256, 256, 0, s_aux>>>(ei);
    scan1_kernel<<<SCAN_BLKS, 1024, 0, s_aux>>>();
    scan2_kernel<<<1, 64, 0, s_aux>>>();
    scan3_kernel<<<(N_NODESC + 255) / 256, 256, 0, s_aux>>>();
    scatter_kernel<<<(N_EDGESC + 255) / 256, 256, 0, s_aux>>>();
    cudaEventRecord(ev_csr, s_aux);
    node_agg_kernel<<<AGG_BLKS, 256, 0, s_aux>>>(x);
    cudaStreamWaitEvent(s_aux, ev_setup, 0);   // weights ready before node GEMM
    mma_gemm<64, 128, 32, 32, true, 1><<<dim3(2, MB64), 256, 0, s_aux>>>(
        pnas, pWns, b_node, (float*)0, phs, (float*)0, 192, 0, N_NODESC, 128, 256);
    cudaEventRecord(ev_node, s_aux);

    // main: edge_agg (needs CSR + AB) -> edge GEMM
    cudaStreamWaitEvent(0, ev_csr, 0);
    edge_agg_kernel<<<AGG_BLKS, 256>>>();
    mma_gemm<64, 128, 32, 32, true, 1><<<dim3(1, MB64), 256>>>(
        peas, pWes, b_ed, (float*)0, phs, (float*)0, 192, 256, N_NODESC, 256, 128);

    // join: fuse needs both h halves (BM=64 -> 782 blocks, better wave balance)
    cudaStreamWaitEvent(0, ev_node, 0);
    mma_gemm<64, 32, 16, 16, true, 0><<<dim3(1, MB64), 256>>>(
        phs, pWfs, b_f1, ph2, (u64*)0, (float*)0, 32, 0, N_NODESC, 384, 32);

    sigmoid_kernel<<<(N_NODESC + 7) / 8, 256>>>(W_f2, b_f2, out);
}

// round 15
// speedup vs baseline: 1.0037x; 1.0037x over previous
#include <cuda_runtime.h>
#include <cuda_bf16.h>

#define N_NODESC 50000
#define N_HALF   25000
#define N_EDGESC 400000
#define SCAN_BLKS 49   // ceil(50000/1024)

typedef unsigned int u32;
typedef unsigned long long u64;

// ---------------- device scratch ----------------
__device__ u64   g_xs[(size_t)N_NODESC * 64];     // x split: [row][pair] (hi|lo packed u64)
__device__ float g_Aarr[(size_t)N_NODESC * 256];  // A-half of edge pre-act (+b_edge)
__device__ float g_Barr[(size_t)N_NODESC * 256];  // B-half (gathered randomly; L2-resident)
__device__ u64   g_nas[(size_t)N_NODESC * 64];    // node_agg split
__device__ u64   g_eas[(size_t)N_NODESC * 128];   // edge_agg split
__device__ u64   g_hs[(size_t)N_NODESC * 192];    // h split
__device__ float g_h2[(size_t)N_NODESC * 32];
__device__ u64   g_Wcs[64 * 512];                 // Wc split  [pair][n]
__device__ u64   g_Wns[64 * 256];
__device__ u64   g_Wes[128 * 128];
__device__ u64   g_Wfs[192 * 32];
__device__ float g_bc[512];
__device__ int   g_count[N_NODESC];
__device__ int   g_off[N_NODESC + 1];
__device__ int   g_cur[N_NODESC];
__device__ int   g_csr[N_EDGESC];
__device__ int   g_ei32[2 * N_EDGESC];
__device__ int   g_bsum[SCAN_BLKS];
__device__ int   g_bpre[SCAN_BLKS];
__device__ int   g_dtype_flag;

// ---------------- helpers ----------------
__device__ __forceinline__ u64 splitpair(float a, float b) {
    __nv_bfloat162 h = __float22bfloat162_rn(make_float2(a, b));
    float2 hf = __bfloat1622float2(h);
    __nv_bfloat162 l = __float22bfloat162_rn(make_float2(a - hf.x, b - hf.y));
    u32 hw = *(u32*)&h, lw = *(u32*)&l;
    return (u64)hw | ((u64)lw << 32);
}

__device__ __forceinline__ void mma16816(float* d, const u32* a, const u32* b) {
    asm volatile(
        "mma.sync.aligned.m16n8k16.row.col.f32.bf16.bf16.f32 "
        "{%0,%1,%2,%3}, {%4,%5,%6,%7}, {%8,%9}, {%0,%1,%2,%3};\n"
        : "+f"(d[0]), "+f"(d[1]), "+f"(d[2]), "+f"(d[3])
        : "r"(a[0]), "r"(a[1]), "r"(a[2]), "r"(a[3]), "r"(b[0]), "r"(b[1]));
}

// 16-byte cp.async (cg = L2 path). pred=false -> zero-fill.
__device__ __forceinline__ void cpasync16(u32 saddr, const void* g, bool pred) {
    int sz = pred ? 16 : 0;
    asm volatile("cp.async.cg.shared.global [%0], [%1], 16, %2;\n"
                 :: "r"(saddr), "l"(g), "r"(sz));
}
#define CP_COMMIT() asm volatile("cp.async.commit_group;\n")
#define CP_WAIT1()  asm volatile("cp.async.wait_group 1;\n")

// ---------------- zero init ----------------
__global__ void zero_kernel() {
    int i = blockIdx.x * blockDim.x + threadIdx.x;
    if (i < N_NODESC) g_count[i] = 0;
    if (i == 0) g_dtype_flag = 0;
}

// ---------------- split weights + split x ----------------
__device__ __forceinline__ float wcval(const float* We, int k, int n) {
    return (n < 256) ? (We[k * 256 + n] - We[(128 + k) * 256 + n])
                     : We[(128 + k) * 256 + (n - 256)];
}

#define SPLITX_BLKS 12500   // N_NODESC*64/256
#define PREPW_BLKS  128

__global__ void setup_kernel(const float* __restrict__ x,
                             const float* __restrict__ We, const float* __restrict__ be,
                             const float* __restrict__ Wn, const float* __restrict__ Wd,
                             const float* __restrict__ Wf) {
    int b = blockIdx.x, tid = threadIdx.x;
    if (b < SPLITX_BLKS) {
        int idx = b * 256 + tid;
        int row = idx >> 6, c = idx & 63;
        float2 v = *(const float2*)(x + (size_t)row * 128 + 2 * c);
        g_xs[idx] = splitpair(v.x, v.y);
    } else {
        int idx = (b - SPLITX_BLKS) * 256 + tid;   // 0..32767
        {
            int c = idx >> 9, n = idx & 511;
            g_Wcs[idx] = splitpair(wcval(We, 2 * c, n), wcval(We, 2 * c + 1, n));
        }
        if (idx < 64 * 256) {
            int c = idx >> 8, n = idx & 255;
            g_Wns[idx] = splitpair(Wn[2 * c * 256 + n], Wn[(2 * c + 1) * 256 + n]);
        }
        if (idx < 128 * 128) {
            int c = idx >> 7, n = idx & 127;
            g_Wes[idx] = splitpair(Wd[2 * c * 128 + n], Wd[(2 * c + 1) * 128 + n]);
        }
        if (idx < 192 * 32) {
            int c = idx >> 5, n = idx & 31;
            g_Wfs[idx] = splitpair(Wf[2 * c * 32 + n], Wf[(2 * c + 1) * 32 + n]);
        }
        if (idx < 512) g_bc[idx] = (idx < 256) ? be[idx] : 0.0f;
    }
}

// ---------------- dtype detect / convert+hist ----------------
__global__ void detect_kernel(const int* __restrict__ w) {
    int acc = 0;
    for (int i = blockIdx.x * blockDim.x + threadIdx.x; i < N_EDGESC; i += gridDim.x * blockDim.x)
        acc |= w[2 * i + 1];
    #pragma unroll
    for (int o = 16; o; o >>= 1) acc |= __shfl_xor_sync(0xffffffffu, acc, o);
    if ((threadIdx.x & 31) == 0 && acc) atomicOr(&g_dtype_flag, 1);
}

__global__ void conv_hist_kernel(const void* __restrict__ ei) {
    int e = blockIdx.x * blockDim.x + threadIdx.x;
    if (e < N_EDGESC) {
        int s, d;
        if (g_dtype_flag) {
            s = ((const int*)ei)[e];
            d = ((const int*)ei)[N_EDGESC + e];
        } else {
            s = (int)((const long long*)ei)[e];
            d = (int)((const long long*)ei)[N_EDGESC + e];
        }
        g_ei32[e] = s;
        g_ei32[N_EDGESC + e] = d;
        atomicAdd(&g_count[d], 1);
    }
}

// ---------------- parallel scan ----------------
__global__ void scan1_kernel() {
    __shared__ int wsum[32], wpre[32];
    int tid = threadIdx.x, lane = tid & 31, w = tid >> 5;
    int i = blockIdx.x * 1024 + tid;
    int orig = (i < N_NODESC) ? g_count[i] : 0;
    int v = orig;
    #pragma unroll
    for (int o = 1; o < 32; o <<= 1) {
        int t = __shfl_up_sync(0xffffffffu, v, o);
        if (lane >= o) v += t;
    }
    if (lane == 31) wsum[w] = v;
    __syncthreads();
    if (w == 0) {
        int s = wsum[lane], sv = s;
        #pragma unroll
        for (int o = 1; o < 32; o <<= 1) {
            int t = __shfl_up_sync(0xffffffffu, sv, o);
            if (lane >= o) sv += t;
        }
        wpre[lane] = sv - s;
        if (lane == 31) g_bsum[blockIdx.x] = sv;
    }
    __syncthreads();
    if (i < N_NODESC) {
        int ex = wpre[w] + v - orig;
        g_off[i] = ex;
        g_cur[i] = ex;
    }
}

__global__ void scan2_kernel() {
    __shared__ int s[64];
    int tid = threadIdx.x;
    int orig = (tid < SCAN_BLKS) ? g_bsum[tid] : 0;
    s[tid] = orig;
    __syncthreads();
    #pragma unroll
    for (int o = 1; o < 64; o <<= 1) {
        int t = (tid >= o) ? s[tid - o] : 0;
        __syncthreads();
        s[tid] += t;
        __syncthreads();
    }
    if (tid < SCAN_BLKS) g_bpre[tid] = s[tid] - orig;
    if (tid == 63) g_off[N_NODESC] = s[63];
}

__global__ void scan3_kernel() {
    int i = blockIdx.x * blockDim.x + threadIdx.x;
    if (i < N_NODESC) {
        int add = g_bpre[i >> 10];
        g_off[i] += add;
        g_cur[i] += add;
    }
}

__global__ void scatter_kernel() {
    int e = blockIdx.x * blockDim.x + threadIdx.x;
    if (e < N_EDGESC) {
        int d = g_ei32[N_EDGESC + e];
        int s = g_ei32[e];
        int p = atomicAdd(&g_cur[d], 1);
        g_csr[p] = s;
    }
}

// ---------------- 2-stage cp.async tensor-core GEMM (proven config) ----------------
// OMODE: 0 = fp32 out, 1 = split-u64 out, 2 = AB dual fp32 (Aarr/Barr)
template <int BM, int BN, int WM, int WN, bool RELU, int OMODE>
__global__ __launch_bounds__(256, 3) void mma_gemm(
    const u64* __restrict__ As,      // [M][K/2]
    const u64* __restrict__ Ws,      // [K/2][Nfull]
    const float* __restrict__ bias,
    float* __restrict__ outf, u64* __restrict__ outs, float* __restrict__ outf2,
    int ldo_p, int ocol0, int M, int K, int Nfull)
{
    constexpr int PC = 8;
    constexpr int SRA = 12;
    constexpr int SRW = BN + 4;
    constexpr int WARPS_N = BN / WN;
    constexpr int MT = WM / 16, NT = WN / 8;
    static_assert((BM / WM) * (BN / WN) == 8, "warp grid must cover block tile");
    constexpr int A_OPS = BM * PC / 2;
    constexpr int W_OPS = PC * BN / 2;
    __shared__ u64 Asm[2][BM][SRA];
    __shared__ u64 Wsm[2][PC][SRW];

    int tid = threadIdx.x;
    int w = tid >> 5, lane = tid & 31;
    int gr = lane >> 2, thc = lane & 3;
    int wm = w / WARPS_N, wn = w % WARPS_N;
    int m0 = blockIdx.y * BM, n0 = blockIdx.x * BN;
    int m0w = wm * WM, n0w = wn * WN;
    int Kp = K >> 1, NS = Kp / PC;

    float d[MT][NT][4] = {};

    auto issue_stage = [&](int buf, int p0) {
        #pragma unroll
        for (int j = 0; j < (A_OPS + 255) / 256; j++) {
            int p = tid + j * 256;
            if ((A_OPS % 256 == 0) || p < A_OPS) {
                int row = p >> 2, dc = (p & 3) * 2;
                u32 sa = (u32)__cvta_generic_to_shared(&Asm[buf][row][dc]);
                cpasync16(sa, As + (size_t)(m0 + row) * Kp + p0 + dc, (m0 + row) < M);
            }
        }
        #pragma unroll
        for (int j = 0; j < (W_OPS + 255) / 256; j++) {
            int p = tid + j * 256;
            if ((W_OPS % 256 == 0) || p < W_OPS) {
                int c = p / (BN / 2), dn = (p % (BN / 2)) * 2;
                u32 sa = (u32)__cvta_generic_to_shared(&Wsm[buf][c][dn]);
                cpasync16(sa, Ws + (size_t)(p0 + c) * Nfull + n0 + dn, true);
            }
        }
        CP_COMMIT();
    };

    issue_stage(0, 0);
    for (int s = 0; s < NS; s++) {
        int buf = s & 1;
        if (s + 1 < NS) issue_stage(buf ^ 1, (s + 1) * PC);
        else CP_COMMIT();
        CP_WAIT1();
        __syncthreads();

        u32 ah[MT][4], al[MT][4], bh[NT][2], bl[NT][2];
        #pragma unroll
        for (int i = 0; i < MT; i++) {
            int r0 = m0w + 16 * i + gr, r1 = r0 + 8;
            u64 v0 = Asm[buf][r0][thc],     v1 = Asm[buf][r1][thc];
            u64 v2 = Asm[buf][r0][thc + 4], v3 = Asm[buf][r1][thc + 4];
            ah[i][0] = (u32)v0; al[i][0] = (u32)(v0 >> 32);
            ah[i][1] = (u32)v1; al[i][1] = (u32)(v1 >> 32);
            ah[i][2] = (u32)v2; al[i][2] = (u32)(v2 >> 32);
            ah[i][3] = (u32)v3; al[i][3] = (u32)(v3 >> 32);
        }
        #pragma unroll
        for (int j = 0; j < NT; j++) {
            int nn = n0w + 8 * j + gr;
            u64 v0 = Wsm[buf][thc][nn], v1 = Wsm[buf][thc + 4][nn];
            bh[j][0] = (u32)v0; bl[j][0] = (u32)(v0 >> 32);
            bh[j][1] = (u32)v1; bl[j][1] = (u32)(v1 >> 32);
        }
        #pragma unroll
        for (int i = 0; i < MT; i++)
            #pragma unroll
            for (int j = 0; j < NT; j++) {
                mma16816(d[i][j], ah[i], bh[j]);
                mma16816(d[i][j], ah[i], bl[j]);
                mma16816(d[i][j], al[i], bh[j]);
            }
        __syncthreads();
    }

    #pragma unroll
    for (int i = 0; i < MT; i++) {
        int row0 = m0 + m0w + 16 * i + gr;
        int row1 = row0 + 8;
        #pragma unroll
        for (int j = 0; j < NT; j++) {
            int col = n0 + n0w + 8 * j + 2 * thc;
            float b0 = bias[col], b1 = bias[col + 1];
            float v00 = d[i][j][0] + b0, v01 = d[i][j][1] + b1;
            float v10 = d[i][j][2] + b0, v11 = d[i][j][3] + b1;
            if (RELU) {
                v00 = fmaxf(v00, 0.0f); v01 = fmaxf(v01, 0.0f);
                v10 = fmaxf(v10, 0.0f); v11 = fmaxf(v11, 0.0f);
            }
            if (OMODE == 0) {
                if (row0 < M) *(float2*)(outf + (size_t)row0 * ldo_p + col) = make_float2(v00, v01);
                if (row1 < M) *(float2*)(outf + (size_t)row1 * ldo_p + col) = make_float2(v10, v11);
            } else if (OMODE == 1) {
                int pidx = (ocol0 + col) >> 1;
                if (row0 < M) outs[(size_t)row0 * ldo_p + pidx] = splitpair(v00, v01);
                if (row1 < M) outs[(size_t)row1 * ldo_p + pidx] = splitpair(v10, v11);
            } else {
                float* dst = (col < 256) ? outf : outf2;
                int cc = (col < 256) ? col : col - 256;
                if (row0 < M) *(float2*)(dst + (size_t)row0 * 256 + cc) = make_float2(v00, v01);
                if (row1 < M) *(float2*)(dst + (size_t)row1 * 256 + cc) = make_float2(v10, v11);
            }
        }
    }
}

// ---------------- node aggregation: na = sum x[src] ----------------
__global__ void node_agg_kernel(const float* __restrict__ x) {
    int gw = (blockIdx.x * blockDim.x + threadIdx.x) >> 5;
    int lane = threadIdx.x & 31;
    if (gw >= N_NODESC) return;
    int beg = g_off[gw], end = g_off[gw + 1];
    float4 na = make_float4(0, 0, 0, 0);
    for (int e = beg; e < end; e++) {
        int s = g_csr[e];
        float4 xv = ((const float4*)(x + (size_t)s * 128))[lane];
        na.x += xv.x; na.y += xv.y; na.z += xv.z; na.w += xv.w;
    }
    u64* nw = g_nas + (size_t)gw * 64;
    nw[2 * lane]     = splitpair(na.x, na.y);
    nw[2 * lane + 1] = splitpair(na.z, na.w);
}

// ---------------- edge aggregation over a row range ----------------
__global__ void edge_agg_kernel(int base, int count) {
    int gw = (blockIdx.x * blockDim.x + threadIdx.x) >> 5;
    int lane = threadIdx.x & 31;
    if (gw >= count) return;
    int d = base + gw;
    int beg = g_off[d], end = g_off[d + 1];
    const float4* Ar = (const float4*)(g_Aarr + (size_t)d * 256);
    float4 a0 = Ar[lane], a1 = Ar[32 + lane];
    float4 e0 = make_float4(0, 0, 0, 0), e1 = e0;
    for (int e = beg; e < end; e++) {
        int s = g_csr[e];
        const float4* br = (const float4*)(g_Barr + (size_t)s * 256);
        float4 b0 = br[lane], b1 = br[32 + lane];
        e0.x += fmaxf(a0.x + b0.x, 0.0f);
        e0.y += fmaxf(a0.y + b0.y, 0.0f);
        e0.z += fmaxf(a0.z + b0.z, 0.0f);
        e0.w += fmaxf(a0.w + b0.w, 0.0f);
        e1.x += fmaxf(a1.x + b1.x, 0.0f);
        e1.y += fmaxf(a1.y + b1.y, 0.0f);
        e1.z += fmaxf(a1.z + b1.z, 0.0f);
        e1.w += fmaxf(a1.w + b1.w, 0.0f);
    }
    u64* ew = g_eas + (size_t)d * 128;
    ew[2 * lane]          = splitpair(e0.x, e0.y);
    ew[2 * lane + 1]      = splitpair(e0.z, e0.w);
    ew[64 + 2 * lane]     = splitpair(e1.x, e1.y);
    ew[64 + 2 * lane + 1] = splitpair(e1.z, e1.w);
}

// ---------------- final sigmoid over a row range ----------------
__global__ void sigmoid_kernel(const float* __restrict__ Wf2, const float* __restrict__ bf2,
                               float* __restrict__ out, int base, int count) {
    int gw = (blockIdx.x * blockDim.x + threadIdx.x) >> 5;
    int lane = threadIdx.x & 31;
    if (gw >= count) return;
    int d = base + gw;
    float t = g_h2[(size_t)d * 32 + lane] * Wf2[lane];
    #pragma unroll
    for (int o = 16; o; o >>= 1) t += __shfl_xor_sync(0xffffffffu, t, o);
    if (lane == 0) out[d] = 1.0f / (1.0f + __expf(-(t + bf2[0])));
}

// ---------------- launch (fork-join + row-half tail pipelining) ----------------
extern "C" void kernel_launch(void* const* d_in, const int* in_sizes, int n_in,
                              void* d_out, int out_size) {
    const float* x  = (const float*)d_in[0];
    const void*  ei = d_in[1];
    const float* W_node = (const float*)d_in[3];
    const float* b_node = (const float*)d_in[4];
    const float* W_edge = (const float*)d_in[5];
    const float* b_edge = (const float*)d_in[6];
    const float* W_ed   = (const float*)d_in[7];
    const float* b_ed   = (const float*)d_in[8];
    const float* W_f1   = (const float*)d_in[9];
    const float* b_f1   = (const float*)d_in[10];
    const float* W_f2   = (const float*)d_in[11];
    const float* b_f2   = (const float*)d_in[12];
    float* out = (float*)d_out;

    u64 *pxs, *pnas, *peas, *phs, *pWcs, *pWns, *pWes, *pWfs;
    float *pA, *pB, *pbc, *ph2;
    cudaGetSymbolAddress((void**)&pxs,  g_xs);
    cudaGetSymbolAddress((void**)&pnas, g_nas);
    cudaGetSymbolAddress((void**)&peas, g_eas);
    cudaGetSymbolAddress((void**)&phs,  g_hs);
    cudaGetSymbolAddress((void**)&pWcs, g_Wcs);
    cudaGetSymbolAddress((void**)&pWns, g_Wns);
    cudaGetSymbolAddress((void**)&pWes, g_Wes);
    cudaGetSymbolAddress((void**)&pWfs, g_Wfs);
    cudaGetSymbolAddress((void**)&pA,   g_Aarr);
    cudaGetSymbolAddress((void**)&pB,   g_Barr);
    cudaGetSymbolAddress((void**)&pbc,  g_bc);
    cudaGetSymbolAddress((void**)&ph2,  g_h2);

    const int MB64  = (N_NODESC + 63) / 64;     // 782
    const int MH64  = (N_HALF + 63) / 64;       // 391
    const int MH128 = (N_HALF + 127) / 128;     // 196

    static cudaStream_t s_aux = 0;
    static cudaEvent_t ev_zero = 0, ev_setup = 0, ev_csr = 0, ev_node = 0,
                       ev_e0 = 0, ev_auxdone = 0;
    if (!s_aux) {
        cudaStreamCreateWithFlags(&s_aux, cudaStreamNonBlocking);
        cudaEventCreateWithFlags(&ev_zero,    cudaEventDisableTiming);
        cudaEventCreateWithFlags(&ev_setup,   cudaEventDisableTiming);
        cudaEventCreateWithFlags(&ev_csr,     cudaEventDisableTiming);
        cudaEventCreateWithFlags(&ev_node,    cudaEventDisableTiming);
        cudaEventCreateWithFlags(&ev_e0,      cudaEventDisableTiming);
        cudaEventCreateWithFlags(&ev_auxdone, cudaEventDisableTiming);
    }

    // main: zero -> fork
    zero_kernel<<<(N_NODESC + 255) / 256, 256>>>();
    cudaEventRecord(ev_zero, 0);
    cudaStreamWaitEvent(s_aux, ev_zero, 0);

    // main: setup (splits + weights) -> AB GEMM
    setup_kernel<<<SPLITX_BLKS + PREPW_BLKS, 256>>>(x, W_edge, b_edge, W_node, W_ed, W_f1);
    cudaEventRecord(ev_setup, 0);
    mma_gemm<64, 128, 32, 32, false, 2><<<dim3(4, MB64), 256>>>(
        pxs, pWcs, pbc, pA, (u64*)0, pB, 0, 0, N_NODESC, 128, 512);

    // aux: CSR chain -> node_agg -> node GEMM (hidden under main's AB)
    detect_kernel<<<256, 256, 0, s_aux>>>((const int*)ei);
    conv_hist_kernel<<<(N_EDGESC + 255) / 256, 256, 0, s_aux>>>(ei);
    scan1_kernel<<<SCAN_BLKS, 1024, 0, s_aux>>>();
    scan2_kernel<<<1, 64, 0, s_aux>>>();
    scan3_kernel<<<(N_NODESC + 255) / 256, 256, 0, s_aux>>>();
    scatter_kernel<<<(N_EDGESC + 255) / 256, 256, 0, s_aux>>>();
    cudaEventRecord(ev_csr, s_aux);
    node_agg_kernel<<<(N_NODESC + 7) / 8, 256, 0, s_aux>>>(x);
    cudaStreamWaitEvent(s_aux, ev_setup, 0);   // weights ready before node GEMM
    mma_gemm<64, 128, 32, 32, true, 1><<<dim3(2, MB64), 256, 0, s_aux>>>(
        pnas, pWns, b_node, (float*)0, phs, (float*)0, 192, 0, N_NODESC, 128, 256);
    cudaEventRecord(ev_node, s_aux);

    // main: edge_agg H0 -> signal -> edge_agg H1
    cudaStreamWaitEvent(0, ev_csr, 0);
    edge_agg_kernel<<<(N_HALF + 7) / 8, 256>>>(0, N_HALF);
    cudaEventRecord(ev_e0, 0);
    edge_agg_kernel<<<(N_HALF + 7) / 8, 256>>>(N_HALF, N_HALF);

    // aux: after node GEMM, process H0 tail: edge GEMM H0 -> fuse H0 -> sigmoid H0
    cudaStreamWaitEvent(s_aux, ev_e0, 0);
    mma_gemm<64, 128, 32, 32, true, 1><<<dim3(1, MH64), 256, 0, s_aux>>>(
        peas, pWes, b_ed, (float*)0, phs, (float*)0, 192, 256, N_HALF, 256, 128);
    mma_gemm<128, 32, 32, 16, true, 0><<<dim3(1, MH128), 256, 0, s_aux>>>(
        phs, pWfs, b_f1, ph2, (u64*)0, (float*)0, 32, 0, N_HALF, 384, 32);
    sigmoid_kernel<<<(N_HALF + 7) / 8, 256, 0, s_aux>>>(W_f2, b_f2, out, 0, N_HALF);
    cudaEventRecord(ev_auxdone, s_aux);

    // main: H1 tail: edge GEMM H1 -> (needs node GEMM) fuse H1 -> sigmoid H1
    mma_gemm<64, 128, 32, 32, true, 1><<<dim3(1, MH64), 256>>>(
        peas + (size_t)N_HALF * 128, pWes, b_ed, (float*)0,
        phs + (size_t)N_HALF * 192, (float*)0, 192, 256, N_HALF, 256, 128);
    cudaStreamWaitEvent(0, ev_node, 0);
    mma_gemm<128, 32, 32, 16, true, 0><<<dim3(1, MH128), 256>>>(
        phs + (size_t)N_HALF * 192, pWfs, b_f1,
        ph2 + (size_t)N_HALF * 32, (u64*)0, (float*)0, 32, 0, N_HALF, 384, 32);
    sigmoid_kernel<<<(N_HALF + 7) / 8, 256>>>(W_f2, b_f2, out, N_HALF, N_HALF);

    // join aux back into main so the captured graph ends after both halves
    cudaStreamWaitEvent(0, ev_auxdone, 0);
}

// round 16
// speedup vs baseline: 1.0303x; 1.0264x over previous
#include <cuda_runtime.h>
#include <cuda_bf16.h>

#define N_NODESC 50000
#define N_EDGESC 400000
#define SCAN_BLKS 49   // ceil(50000/1024)

typedef unsigned int u32;
typedef unsigned long long u64;

// ---------------- device scratch ----------------
__device__ u64   g_xs[(size_t)N_NODESC * 64];     // x split: [row][pair] (hi|lo packed u64)
__device__ float g_Aarr[(size_t)N_NODESC * 256];  // A-half of edge pre-act (+b_edge)
__device__ float g_Barr[(size_t)N_NODESC * 256];  // B-half (gathered randomly; L2-resident)
__device__ u64   g_nas[(size_t)N_NODESC * 64];    // node_agg split
__device__ u64   g_eas[(size_t)N_NODESC * 128];   // edge_agg split
__device__ u64   g_hs[(size_t)N_NODESC * 192];    // h split
__device__ u64   g_Wcs[64 * 512];                 // Wc split  [pair][n]
__device__ u64   g_Wns[64 * 256];
__device__ u64   g_Wes[128 * 128];
__device__ u64   g_Wfs[192 * 32];
__device__ float g_bc[512];
__device__ int   g_count[N_NODESC];
__device__ int   g_off[N_NODESC + 1];
__device__ int   g_cur[N_NODESC];
__device__ int   g_csr[N_EDGESC];
__device__ int   g_ei32[2 * N_EDGESC];
__device__ int   g_bsum[SCAN_BLKS];
__device__ int   g_bpre[SCAN_BLKS];
__device__ int   g_dtype_flag;

// ---------------- helpers ----------------
__device__ __forceinline__ u64 splitpair(float a, float b) {
    __nv_bfloat162 h = __float22bfloat162_rn(make_float2(a, b));
    float2 hf = __bfloat1622float2(h);
    __nv_bfloat162 l = __float22bfloat162_rn(make_float2(a - hf.x, b - hf.y));
    u32 hw = *(u32*)&h, lw = *(u32*)&l;
    return (u64)hw | ((u64)lw << 32);
}

__device__ __forceinline__ void mma16816(float* d, const u32* a, const u32* b) {
    asm volatile(
        "mma.sync.aligned.m16n8k16.row.col.f32.bf16.bf16.f32 "
        "{%0,%1,%2,%3}, {%4,%5,%6,%7}, {%8,%9}, {%0,%1,%2,%3};\n"
        : "+f"(d[0]), "+f"(d[1]), "+f"(d[2]), "+f"(d[3])
        : "r"(a[0]), "r"(a[1]), "r"(a[2]), "r"(a[3]), "r"(b[0]), "r"(b[1]));
}

// 16-byte cp.async (cg = L2 path). pred=false -> zero-fill.
__device__ __forceinline__ void cpasync16(u32 saddr, const void* g, bool pred) {
    int sz = pred ? 16 : 0;
    asm volatile("cp.async.cg.shared.global [%0], [%1], 16, %2;\n"
                 :: "r"(saddr), "l"(g), "r"(sz));
}
#define CP_COMMIT() asm volatile("cp.async.commit_group;\n")
#define CP_WAIT1()  asm volatile("cp.async.wait_group 1;\n")

// ---------------- zero init ----------------
__global__ void zero_kernel() {
    int i = blockIdx.x * blockDim.x + threadIdx.x;
    if (i < N_NODESC) g_count[i] = 0;
    if (i == 0) g_dtype_flag = 0;
}

// ---------------- split weights + split x ----------------
__device__ __forceinline__ float wcval(const float* We, int k, int n) {
    return (n < 256) ? (We[k * 256 + n] - We[(128 + k) * 256 + n])
                     : We[(128 + k) * 256 + (n - 256)];
}

#define SPLITX_BLKS 12500   // N_NODESC*64/256
#define PREPW_BLKS  128

__global__ void setup_kernel(const float* __restrict__ x,
                             const float* __restrict__ We, const float* __restrict__ be,
                             const float* __restrict__ Wn, const float* __restrict__ Wd,
                             const float* __restrict__ Wf) {
    int b = blockIdx.x, tid = threadIdx.x;
    if (b < SPLITX_BLKS) {
        int idx = b * 256 + tid;
        int row = idx >> 6, c = idx & 63;
        float2 v = *(const float2*)(x + (size_t)row * 128 + 2 * c);
        g_xs[idx] = splitpair(v.x, v.y);
    } else {
        int idx = (b - SPLITX_BLKS) * 256 + tid;   // 0..32767
        {
            int c = idx >> 9, n = idx & 511;
            g_Wcs[idx] = splitpair(wcval(We, 2 * c, n), wcval(We, 2 * c + 1, n));
        }
        if (idx < 64 * 256) {
            int c = idx >> 8, n = idx & 255;
            g_Wns[idx] = splitpair(Wn[2 * c * 256 + n], Wn[(2 * c + 1) * 256 + n]);
        }
        if (idx < 128 * 128) {
            int c = idx >> 7, n = idx & 127;
            g_Wes[idx] = splitpair(Wd[2 * c * 128 + n], Wd[(2 * c + 1) * 128 + n]);
        }
        if (idx < 192 * 32) {
            int c = idx >> 5, n = idx & 31;
            g_Wfs[idx] = splitpair(Wf[2 * c * 32 + n], Wf[(2 * c + 1) * 32 + n]);
        }
        if (idx < 512) g_bc[idx] = (idx < 256) ? be[idx] : 0.0f;
    }
}

// ---------------- dtype detect / convert+hist ----------------
__global__ void detect_kernel(const int* __restrict__ w) {
    int acc = 0;
    for (int i = blockIdx.x * blockDim.x + threadIdx.x; i < N_EDGESC; i += gridDim.x * blockDim.x)
        acc |= w[2 * i + 1];
    #pragma unroll
    for (int o = 16; o; o >>= 1) acc |= __shfl_xor_sync(0xffffffffu, acc, o);
    if ((threadIdx.x & 31) == 0 && acc) atomicOr(&g_dtype_flag, 1);
}

__global__ void conv_hist_kernel(const void* __restrict__ ei) {
    int e = blockIdx.x * blockDim.x + threadIdx.x;
    if (e < N_EDGESC) {
        int s, d;
        if (g_dtype_flag) {
            s = ((const int*)ei)[e];
            d = ((const int*)ei)[N_EDGESC + e];
        } else {
            s = (int)((const long long*)ei)[e];
            d = (int)((const long long*)ei)[N_EDGESC + e];
        }
        g_ei32[e] = s;
        g_ei32[N_EDGESC + e] = d;
        atomicAdd(&g_count[d], 1);
    }
}

// ---------------- parallel scan ----------------
__global__ void scan1_kernel() {
    __shared__ int wsum[32], wpre[32];
    int tid = threadIdx.x, lane = tid & 31, w = tid >> 5;
    int i = blockIdx.x * 1024 + tid;
    int orig = (i < N_NODESC) ? g_count[i] : 0;
    int v = orig;
    #pragma unroll
    for (int o = 1; o < 32; o <<= 1) {
        int t = __shfl_up_sync(0xffffffffu, v, o);
        if (lane >= o) v += t;
    }
    if (lane == 31) wsum[w] = v;
    __syncthreads();
    if (w == 0) {
        int s = wsum[lane], sv = s;
        #pragma unroll
        for (int o = 1; o < 32; o <<= 1) {
            int t = __shfl_up_sync(0xffffffffu, sv, o);
            if (lane >= o) sv += t;
        }
        wpre[lane] = sv - s;
        if (lane == 31) g_bsum[blockIdx.x] = sv;
    }
    __syncthreads();
    if (i < N_NODESC) {
        int ex = wpre[w] + v - orig;
        g_off[i] = ex;
        g_cur[i] = ex;
    }
}

__global__ void scan2_kernel() {
    __shared__ int s[64];
    int tid = threadIdx.x;
    int orig = (tid < SCAN_BLKS) ? g_bsum[tid] : 0;
    s[tid] = orig;
    __syncthreads();
    #pragma unroll
    for (int o = 1; o < 64; o <<= 1) {
        int t = (tid >= o) ? s[tid - o] : 0;
        __syncthreads();
        s[tid] += t;
        __syncthreads();
    }
    if (tid < SCAN_BLKS) g_bpre[tid] = s[tid] - orig;
    if (tid == 63) g_off[N_NODESC] = s[63];
}

__global__ void scan3_kernel() {
    int i = blockIdx.x * blockDim.x + threadIdx.x;
    if (i < N_NODESC) {
        int add = g_bpre[i >> 10];
        g_off[i] += add;
        g_cur[i] += add;
    }
}

__global__ void scatter_kernel() {
    int e = blockIdx.x * blockDim.x + threadIdx.x;
    if (e < N_EDGESC) {
        int d = g_ei32[N_EDGESC + e];
        int s = g_ei32[e];
        int p = atomicAdd(&g_cur[d], 1);
        g_csr[p] = s;
    }
}

// ---------------- 2-stage cp.async tensor-core GEMM ----------------
// OMODE: 0 = fp32 out, 1 = split-u64 out, 2 = AB dual fp32 (Aarr/Barr),
//        3 = fused head: dot columns with Wf2x, sigmoid(+bf2x), write out[row]
template <int BM, int BN, int WM, int WN, bool RELU, int OMODE>
__global__ __launch_bounds__(256, 3) void mma_gemm(
    const u64* __restrict__ As,      // [M][K/2]
    const u64* __restrict__ Ws,      // [K/2][Nfull]
    const float* __restrict__ bias,
    float* __restrict__ outf, u64* __restrict__ outs, float* __restrict__ outf2,
    int ldo_p, int ocol0, int M, int K, int Nfull,
    const float* __restrict__ Wf2x, const float* __restrict__ bf2x)
{
    constexpr int PC = 8;
    constexpr int SRA = 12;
    constexpr int SRW = BN + 4;
    constexpr int WARPS_N = BN / WN;
    constexpr int MT = WM / 16, NT = WN / 8;
    static_assert((BM / WM) * (BN / WN) == 8, "warp grid must cover block tile");
    constexpr int A_OPS = BM * PC / 2;
    constexpr int W_OPS = PC * BN / 2;
    __shared__ u64 Asm[2][BM][SRA];
    __shared__ u64 Wsm[2][PC][SRW];
    __shared__ float srow[BM];       // OMODE 3: per-row dot accumulator

    int tid = threadIdx.x;
    int w = tid >> 5, lane = tid & 31;
    int gr = lane >> 2, thc = lane & 3;
    int wm = w / WARPS_N, wn = w % WARPS_N;
    int m0 = blockIdx.y * BM, n0 = blockIdx.x * BN;
    int m0w = wm * WM, n0w = wn * WN;
    int Kp = K >> 1, NS = Kp / PC;

    if (OMODE == 3) {
        for (int r = tid; r < BM; r += 256) srow[r] = 0.0f;
    }

    float d[MT][NT][4] = {};

    auto issue_stage = [&](int buf, int p0) {
        #pragma unroll
        for (int j = 0; j < (A_OPS + 255) / 256; j++) {
            int p = tid + j * 256;
            if ((A_OPS % 256 == 0) || p < A_OPS) {
                int row = p >> 2, dc = (p & 3) * 2;
                u32 sa = (u32)__cvta_generic_to_shared(&Asm[buf][row][dc]);
                cpasync16(sa, As + (size_t)(m0 + row) * Kp + p0 + dc, (m0 + row) < M);
            }
        }
        #pragma unroll
        for (int j = 0; j < (W_OPS + 255) / 256; j++) {
            int p = tid + j * 256;
            if ((W_OPS % 256 == 0) || p < W_OPS) {
                int c = p / (BN / 2), dn = (p % (BN / 2)) * 2;
                u32 sa = (u32)__cvta_generic_to_shared(&Wsm[buf][c][dn]);
                cpasync16(sa, Ws + (size_t)(p0 + c) * Nfull + n0 + dn, true);
            }
        }
        CP_COMMIT();
    };

    issue_stage(0, 0);
    for (int s = 0; s < NS; s++) {
        int buf = s & 1;
        if (s + 1 < NS) issue_stage(buf ^ 1, (s + 1) * PC);
        else CP_COMMIT();
        CP_WAIT1();
        __syncthreads();

        u32 ah[MT][4], al[MT][4], bh[NT][2], bl[NT][2];
        #pragma unroll
        for (int i = 0; i < MT; i++) {
            int r0 = m0w + 16 * i + gr, r1 = r0 + 8;
            u64 v0 = Asm[buf][r0][thc],     v1 = Asm[buf][r1][thc];
            u64 v2 = Asm[buf][r0][thc + 4], v3 = Asm[buf][r1][thc + 4];
            ah[i][0] = (u32)v0; al[i][0] = (u32)(v0 >> 32);
            ah[i][1] = (u32)v1; al[i][1] = (u32)(v1 >> 32);
            ah[i][2] = (u32)v2; al[i][2] = (u32)(v2 >> 32);
            ah[i][3] = (u32)v3; al[i][3] = (u32)(v3 >> 32);
        }
        #pragma unroll
        for (int j = 0; j < NT; j++) {
            int nn = n0w + 8 * j + gr;
            u64 v0 = Wsm[buf][thc][nn], v1 = Wsm[buf][thc + 4][nn];
            bh[j][0] = (u32)v0; bl[j][0] = (u32)(v0 >> 32);
            bh[j][1] = (u32)v1; bl[j][1] = (u32)(v1 >> 32);
        }
        #pragma unroll
        for (int i = 0; i < MT; i++)
            #pragma unroll
            for (int j = 0; j < NT; j++) {
                mma16816(d[i][j], ah[i], bh[j]);
                mma16816(d[i][j], ah[i], bl[j]);
                mma16816(d[i][j], al[i], bh[j]);
            }
        __syncthreads();
    }

    #pragma unroll
    for (int i = 0; i < MT; i++) {
        int row0 = m0 + m0w + 16 * i + gr;
        int row1 = row0 + 8;
        float p0 = 0.0f, p1 = 0.0f;   // OMODE 3 partial dots
        #pragma unroll
        for (int j = 0; j < NT; j++) {
            int col = n0 + n0w + 8 * j + 2 * thc;
            float b0 = bias[col], b1 = bias[col + 1];
            float v00 = d[i][j][0] + b0, v01 = d[i][j][1] + b1;
            float v10 = d[i][j][2] + b0, v11 = d[i][j][3] + b1;
            if (RELU) {
                v00 = fmaxf(v00, 0.0f); v01 = fmaxf(v01, 0.0f);
                v10 = fmaxf(v10, 0.0f); v11 = fmaxf(v11, 0.0f);
            }
            if (OMODE == 0) {
                if (row0 < M) *(float2*)(outf + (size_t)row0 * ldo_p + col) = make_float2(v00, v01);
                if (row1 < M) *(float2*)(outf + (size_t)row1 * ldo_p + col) = make_float2(v10, v11);
            } else if (OMODE == 1) {
                int pidx = (ocol0 + col) >> 1;
                if (row0 < M) outs[(size_t)row0 * ldo_p + pidx] = splitpair(v00, v01);
                if (row1 < M) outs[(size_t)row1 * ldo_p + pidx] = splitpair(v10, v11);
            } else if (OMODE == 2) {
                float* dst = (col < 256) ? outf : outf2;
                int cc = (col < 256) ? col : col - 256;
                if (row0 < M) *(float2*)(dst + (size_t)row0 * 256 + cc) = make_float2(v00, v01);
                if (row1 < M) *(float2*)(dst + (size_t)row1 * 256 + cc) = make_float2(v10, v11);
            } else {
                float w0 = Wf2x[col], w1 = Wf2x[col + 1];
                p0 += v00 * w0 + v01 * w1;
                p1 += v10 * w0 + v11 * w1;
            }
        }
        if (OMODE == 3) {
            // quad-reduce across thc (lanes sharing gr): 16-col partial per warp
            p0 += __shfl_xor_sync(0xffffffffu, p0, 1);
            p0 += __shfl_xor_sync(0xffffffffu, p0, 2);
            p1 += __shfl_xor_sync(0xffffffffu, p1, 1);
            p1 += __shfl_xor_sync(0xffffffffu, p1, 2);
            if (thc == 0) {
                // exactly WARPS_N(=2) contributions per row; 2-operand fp32 add
                // is commutative -> deterministic
                atomicAdd(&srow[m0w + 16 * i + gr], p0);
                atomicAdd(&srow[m0w + 16 * i + gr + 8], p1);
            }
        }
    }

    if (OMODE == 3) {
        __syncthreads();
        float badd = bf2x[0];
        for (int r = tid; r < BM; r += 256) {
            int row = m0 + r;
            if (row < M) outf[row] = 1.0f / (1.0f + __expf(-(srow[r] + badd)));
        }
    }
}

// ---------------- node aggregation: na = sum x[src] ----------------
__global__ void node_agg_kernel(const float* __restrict__ x) {
    int gw = (blockIdx.x * blockDim.x + threadIdx.x) >> 5;
    int lane = threadIdx.x & 31;
    if (gw >= N_NODESC) return;
    int beg = g_off[gw], end = g_off[gw + 1];
    float4 na = make_float4(0, 0, 0, 0);
    for (int e = beg; e < end; e++) {
        int s = g_csr[e];
        float4 xv = ((const float4*)(x + (size_t)s * 128))[lane];
        na.x += xv.x; na.y += xv.y; na.z += xv.z; na.w += xv.w;
    }
    u64* nw = g_nas + (size_t)gw * 64;
    nw[2 * lane]     = splitpair(na.x, na.y);
    nw[2 * lane + 1] = splitpair(na.z, na.w);
}

// ---------------- edge aggregation (warp-per-dst, unroll x2) ----------------
__global__ void edge_agg_kernel() {
    int gw = (blockIdx.x * blockDim.x + threadIdx.x) >> 5;
    int lane = threadIdx.x & 31;
    if (gw >= N_NODESC) return;
    int beg = g_off[gw], end = g_off[gw + 1];
    const float4* Ar = (const float4*)(g_Aarr + (size_t)gw * 256);
    float4 a0 = Ar[lane], a1 = Ar[32 + lane];
    float4 e0 = make_float4(0, 0, 0, 0), e1 = e0;
    int e = beg;
    for (; e + 1 < end; e += 2) {
        int s0 = g_csr[e], s1 = g_csr[e + 1];
        const float4* br0 = (const float4*)(g_Barr + (size_t)s0 * 256);
        const float4* br1 = (const float4*)(g_Barr + (size_t)s1 * 256);
        float4 p0 = br0[lane], p1 = br0[32 + lane];
        float4 q0 = br1[lane], q1 = br1[32 + lane];
        e0.x += fmaxf(a0.x + p0.x, 0.0f) + fmaxf(a0.x + q0.x, 0.0f);
        e0.y += fmaxf(a0.y + p0.y, 0.0f) + fmaxf(a0.y + q0.y, 0.0f);
        e0.z += fmaxf(a0.z + p0.z, 0.0f) + fmaxf(a0.z + q0.z, 0.0f);
        e0.w += fmaxf(a0.w + p0.w, 0.0f) + fmaxf(a0.w + q0.w, 0.0f);
        e1.x += fmaxf(a1.x + p1.x, 0.0f) + fmaxf(a1.x + q1.x, 0.0f);
        e1.y += fmaxf(a1.y + p1.y, 0.0f) + fmaxf(a1.y + q1.y, 0.0f);
        e1.z += fmaxf(a1.z + p1.z, 0.0f) + fmaxf(a1.z + q1.z, 0.0f);
        e1.w += fmaxf(a1.w + p1.w, 0.0f) + fmaxf(a1.w + q1.w, 0.0f);
    }
    if (e < end) {
        int s0 = g_csr[e];
        const float4* br0 = (const float4*)(g_Barr + (size_t)s0 * 256);
        float4 p0 = br0[lane], p1 = br0[32 + lane];
        e0.x += fmaxf(a0.x + p0.x, 0.0f);
        e0.y += fmaxf(a0.y + p0.y, 0.0f);
        e0.z += fmaxf(a0.z + p0.z, 0.0f);
        e0.w += fmaxf(a0.w + p0.w, 0.0f);
        e1.x += fmaxf(a1.x + p1.x, 0.0f);
        e1.y += fmaxf(a1.y + p1.y, 0.0f);
        e1.z += fmaxf(a1.z + p1.z, 0.0f);
        e1.w += fmaxf(a1.w + p1.w, 0.0f);
    }
    u64* ew = g_eas + (size_t)gw * 128;
    ew[2 * lane]          = splitpair(e0.x, e0.y);
    ew[2 * lane + 1]      = splitpair(e0.z, e0.w);
    ew[64 + 2 * lane]     = splitpair(e1.x, e1.y);
    ew[64 + 2 * lane + 1] = splitpair(e1.z, e1.w);
}

// ---------------- launch (two-branch fork-join; graph-capture-legal) ----------------
extern "C" void kernel_launch(void* const* d_in, const int* in_sizes, int n_in,
                              void* d_out, int out_size) {
    const float* x  = (const float*)d_in[0];
    const void*  ei = d_in[1];
    const float* W_node = (const float*)d_in[3];
    const float* b_node = (const float*)d_in[4];
    const float* W_edge = (const float*)d_in[5];
    const float* b_edge = (const float*)d_in[6];
    const float* W_ed   = (const float*)d_in[7];
    const float* b_ed   = (const float*)d_in[8];
    const float* W_f1   = (const float*)d_in[9];
    const float* b_f1   = (const float*)d_in[10];
    const float* W_f2   = (const float*)d_in[11];
    const float* b_f2   = (const float*)d_in[12];
    float* out = (float*)d_out;

    u64 *pxs, *pnas, *peas, *phs, *pWcs, *pWns, *pWes, *pWfs;
    float *pA, *pB, *pbc;
    cudaGetSymbolAddress((void**)&pxs,  g_xs);
    cudaGetSymbolAddress((void**)&pnas, g_nas);
    cudaGetSymbolAddress((void**)&peas, g_eas);
    cudaGetSymbolAddress((void**)&phs,  g_hs);
    cudaGetSymbolAddress((void**)&pWcs, g_Wcs);
    cudaGetSymbolAddress((void**)&pWns, g_Wns);
    cudaGetSymbolAddress((void**)&pWes, g_Wes);
    cudaGetSymbolAddress((void**)&pWfs, g_Wfs);
    cudaGetSymbolAddress((void**)&pA,   g_Aarr);
    cudaGetSymbolAddress((void**)&pB,   g_Barr);
    cudaGetSymbolAddress((void**)&pbc,  g_bc);

    const int MB64  = (N_NODESC + 63) / 64;     // 782
    const int MB128 = (N_NODESC + 127) / 128;   // 391
    const float* FZ = (const float*)0;

    static cudaStream_t s_aux = 0;
    static cudaEvent_t ev_zero = 0, ev_setup = 0, ev_csr = 0, ev_node = 0;
    if (!s_aux) {
        cudaStreamCreateWithFlags(&s_aux, cudaStreamNonBlocking);
        cudaEventCreateWithFlags(&ev_zero,  cudaEventDisableTiming);
        cudaEventCreateWithFlags(&ev_setup, cudaEventDisableTiming);
        cudaEventCreateWithFlags(&ev_csr,   cudaEventDisableTiming);
        cudaEventCreateWithFlags(&ev_node,  cudaEventDisableTiming);
    }

    // main: zero -> fork
    zero_kernel<<<(N_NODESC + 255) / 256, 256>>>();
    cudaEventRecord(ev_zero, 0);
    cudaStreamWaitEvent(s_aux, ev_zero, 0);

    // main: setup (splits + weights) -> AB GEMM
    setup_kernel<<<SPLITX_BLKS + PREPW_BLKS, 256>>>(x, W_edge, b_edge, W_node, W_ed, W_f1);
    cudaEventRecord(ev_setup, 0);
    mma_gemm<64, 128, 32, 32, false, 2><<<dim3(4, MB64), 256>>>(
        pxs, pWcs, pbc, pA, (u64*)0, pB, 0, 0, N_NODESC, 128, 512, FZ, FZ);

    // aux: CSR chain -> node_agg -> node GEMM (hidden under main's AB+edge_agg)
    detect_kernel<<<256, 256, 0, s_aux>>>((const int*)ei);
    conv_hist_kernel<<<(N_EDGESC + 255) / 256, 256, 0, s_aux>>>(ei);
    scan1_kernel<<<SCAN_BLKS, 1024, 0, s_aux>>>();
    scan2_kernel<<<1, 64, 0, s_aux>>>();
    scan3_kernel<<<(N_NODESC + 255) / 256, 256, 0, s_aux>>>();
    scatter_kernel<<<(N_EDGESC + 255) / 256, 256, 0, s_aux>>>();
    cudaEventRecord(ev_csr, s_aux);
    node_agg_kernel<<<(N_NODESC + 7) / 8, 256, 0, s_aux>>>(x);
    cudaStreamWaitEvent(s_aux, ev_setup, 0);   // weights ready before node GEMM
    mma_gemm<64, 128, 32, 32, true, 1><<<dim3(2, MB64), 256, 0, s_aux>>>(
        pnas, pWns, b_node, (float*)0, phs, (float*)0, 192, 0, N_NODESC, 128, 256, FZ, FZ);
    cudaEventRecord(ev_node, s_aux);

    // main: edge_agg (needs CSR + AB) -> edge GEMM
    cudaStreamWaitEvent(0, ev_csr, 0);
    edge_agg_kernel<<<(N_NODESC + 7) / 8, 256>>>();
    mma_gemm<64, 128, 32, 32, true, 1><<<dim3(1, MB64), 256>>>(
        peas, pWes, b_ed, (float*)0, phs, (float*)0, 192, 256, N_NODESC, 256, 128, FZ, FZ);

    // join: fused head (fuse GEMM + dot + sigmoid in one kernel)
    cudaStreamWaitEvent(0, ev_node, 0);
    mma_gemm<128, 32, 32, 16, true, 3><<<dim3(1, MB128), 256>>>(
        phs, pWfs, b_f1, out, (u64*)0, (float*)0, 32, 0, N_NODESC, 384, 32, W_f2, b_f2);
}